// round 17
// baseline (speedup 1.0000x reference)
#include <cuda_runtime.h>
#include <cuda_bf16.h>
#include <cstdint>

constexpr int B = 2, C = 2, D = 160, H = 192, W = 224;
constexpr int HW  = H * W;          // 43008
constexpr int DHW = D * H * W;      // 6,881,280
constexpr int VPT = 4;              // z-chain length per thread

__device__ __forceinline__ float lerpf(float a, float b, float t) {
    return fmaf(t, b - a, a);
}

// Guaranteed-predicated global load: returns *p when cond!=0, else fallback.
// Emits @p LDG (dest preserved when predicated off) — never LDG+SEL.
__device__ __forceinline__ float ldg_if(const float* p, unsigned cond, float fallback) {
    float v = fallback;
    asm volatile("{\n\t"
                 ".reg .pred p0;\n\t"
                 "setp.ne.u32 p0, %1, 0;\n\t"
                 "@p0 ld.global.nc.f32 %0, [%2];\n\t"
                 "}"
                 : "+f"(v) : "r"(cond), "l"(p));
    return v;
}

__device__ __forceinline__ float tri(float l00, float l01, float l10, float l11,
                                     float u00, float u01, float u10, float u11,
                                     float fx, float fy, float fz) {
    float m0 = lerpf(lerpf(l00, l01, fx), lerpf(l10, l11, fx), fy);
    float m1 = lerpf(lerpf(u00, u01, fx), lerpf(u10, u11, fx), fy);
    return lerpf(m0, m1, fz);
}

__global__ __launch_bounds__(224, 8)
void affine_grid_sample_kernel(const float* __restrict__ src,
                               const float* __restrict__ mat,
                               float* __restrict__ out)
{
    const int w  = threadIdx.x;      // 0..W-1
    const int h  = blockIdx.y;       // 0..H-1
    const int zz = blockIdx.z;       // 0..B*(D/VPT)-1
    const int b  = (zz >= D / VPT) ? 1 : 0;
    const int d0 = VPT * (zz - (b ? D / VPT : 0));

    const float4* m4 = (const float4*)(mat + b * 12);
    const float4 r0 = __ldg(m4 + 0);
    const float4 r1 = __ldg(m4 + 1);
    const float4 r2 = __ldg(m4 + 2);

    const float x = fmaf((float)w,  2.0f / (W - 1), -1.0f);
    const float y = fmaf((float)h,  2.0f / (H - 1), -1.0f);
    const float z = fmaf((float)d0, 2.0f / (D - 1), -1.0f);

    const float gx = fmaf(r0.x, x, fmaf(r0.y, y, fmaf(r0.z, z, r0.w * (1.0f / D))));
    const float gy = fmaf(r1.x, x, fmaf(r1.y, y, fmaf(r1.z, z, r1.w * (1.0f / H))));
    const float gz = fmaf(r2.x, x, fmaf(r2.y, y, fmaf(r2.z, z, r2.w * (1.0f / W))));

    const float sW = 0.5f * (W - 1), sH = 0.5f * (H - 1), sD = 0.5f * (D - 1);
    const float ix0 = (gx + 1.0f) * sW;
    const float iy0 = (gy + 1.0f) * sH;
    const float iz0 = (gz + 1.0f) * sD;

    const float ddz = 2.0f / (D - 1);
    const float dix = r0.z * (ddz * sW);
    const float diy = r1.z * (ddz * sH);
    const float diz = r2.z * (ddz * sD);

    // one pass: interior flag + packed share-predicate bitmask (bit v set
    // when voxel v's lower plane does NOT coincide with v-1's upper plane)
    unsigned needmask = 0;
    bool interior = true;
    {
        int pxx = 0, pyy = 0, pzz_ = 0;
#pragma unroll
        for (int v = 0; v < VPT; ++v) {
            const float ix = fmaf((float)v, dix, ix0);
            const float iy = fmaf((float)v, diy, iy0);
            const float iz = fmaf((float)v, diz, iz0);
            const int x0 = (int)floorf(ix);
            const int y0 = (int)floorf(iy);
            const int z0 = (int)floorf(iz);
            interior &= ((unsigned)x0 < (unsigned)(W - 1)) &
                        ((unsigned)y0 < (unsigned)(H - 1)) &
                        ((unsigned)z0 < (unsigned)(D - 1));
            if (v > 0) {
                const bool sh = (z0 == pzz_ + 1) & (y0 == pyy) & (x0 == pxx);
                needmask |= ((unsigned)(!sh)) << v;
            }
            pxx = x0; pyy = y0; pzz_ = z0;
        }
    }

    const float* sb = src + (size_t)b * (size_t)(C * DHW);
    const size_t ob = (size_t)b * (size_t)(C * DHW) + (size_t)((d0 * H + h) * W + w);

    if (interior) {
        // ===== fast path: chain-shared lower planes, @p-predicated fixups =====
        // per-voxel coords are recomputed per channel (FMA pipe is idle;
        // registers are the scarce resource)
#pragma unroll
        for (int ch = 0; ch < 2; ++ch) {
            const float* base = sb + (size_t)ch * DHW;
            float* o = out + (size_t)ch * DHW + ob;

            float cu00 = 0.f, cu01 = 0.f, cu10 = 0.f, cu11 = 0.f; // carried upper plane

#pragma unroll
            for (int v = 0; v < VPT; ++v) {
                const float ix = fmaf((float)v, dix, ix0);
                const float iy = fmaf((float)v, diy, iy0);
                const float iz = fmaf((float)v, diz, iz0);
                const float flx = floorf(ix), fly = floorf(iy), flz = floorf(iz);
                const float fx = ix - flx, fy = iy - fly, fz = iz - flz;
                const int x0 = (int)flx, y0 = (int)fly, z0 = (int)flz;

                const float* p = base + ((z0 * H + y0) * W + x0);

                // upper plane: always loaded
                const float u00 = __ldg(p + HW);
                const float u01 = __ldg(p + HW + 1);
                const float u10 = __ldg(p + HW + W);
                const float u11 = __ldg(p + HW + W + 1);

                float l00, l01, l10, l11;
                if (v == 0) {
                    l00 = __ldg(p);
                    l01 = __ldg(p + 1);
                    l10 = __ldg(p + W);
                    l11 = __ldg(p + W + 1);
                } else {
                    const unsigned need = (needmask >> v) & 1u;
                    l00 = ldg_if(p,         need, cu00);
                    l01 = ldg_if(p + 1,     need, cu01);
                    l10 = ldg_if(p + W,     need, cu10);
                    l11 = ldg_if(p + W + 1, need, cu11);
                }

                o[(size_t)v * HW] = tri(l00, l01, l10, l11,
                                        u00, u01, u10, u11, fx, fy, fz);

                cu00 = u00; cu01 = u01; cu10 = u10; cu11 = u11;
            }

            // keep channel 1's loads out of channel 0's register window
            asm volatile("" ::: "memory");
        }
        return;
    }

    // ===== border path: per-voxel fully predicated, zero padding =====
#pragma unroll
    for (int v = 0; v < VPT; ++v) {
        const float ix = fmaf((float)v, dix, ix0);
        const float iy = fmaf((float)v, diy, iy0);
        const float iz = fmaf((float)v, diz, iz0);
        const float flx = floorf(ix), fly = floorf(iy), flz = floorf(iz);
        const float gfx = ix - flx, gfy = iy - fly, gfz = iz - flz;
        const int x0 = (int)flx, y0 = (int)fly, z0 = (int)flz;

        const bool vx0 = (unsigned)x0       < (unsigned)W;
        const bool vx1 = (unsigned)(x0 + 1) < (unsigned)W;
        const bool vy0 = (unsigned)y0       < (unsigned)H;
        const bool vy1 = (unsigned)(y0 + 1) < (unsigned)H;
        const bool vz0 = (unsigned)z0       < (unsigned)D;
        const bool vz1 = (unsigned)(z0 + 1) < (unsigned)D;

        const bool p000 = vz0 & vy0 & vx0, p001 = vz0 & vy0 & vx1;
        const bool p010 = vz0 & vy1 & vx0, p011 = vz0 & vy1 & vx1;
        const bool p100 = vz1 & vy0 & vx0, p101 = vz1 & vy0 & vx1;
        const bool p110 = vz1 & vy1 & vx0, p111 = vz1 & vy1 & vx1;

        const float* pbase = sb + ((size_t)((z0 * H + y0) * W + x0));

#pragma unroll
        for (int ch = 0; ch < 2; ++ch) {
            const float* p = pbase + (size_t)ch * DHW;

            float l00 = p000 ? __ldg(p)              : 0.0f;
            float l01 = p001 ? __ldg(p + 1)          : 0.0f;
            float l10 = p010 ? __ldg(p + W)          : 0.0f;
            float l11 = p011 ? __ldg(p + W + 1)      : 0.0f;
            float u00 = p100 ? __ldg(p + HW)         : 0.0f;
            float u01 = p101 ? __ldg(p + HW + 1)     : 0.0f;
            float u10 = p110 ? __ldg(p + HW + W)     : 0.0f;
            float u11 = p111 ? __ldg(p + HW + W + 1) : 0.0f;

            out[ob + (size_t)v * HW + (size_t)ch * DHW] =
                tri(l00, l01, l10, l11, u00, u01, u10, u11, gfx, gfy, gfz);
        }
    }
}

extern "C" void kernel_launch(void* const* d_in, const int* in_sizes, int n_in,
                              void* d_out, int out_size)
{
    const float* src = (const float*)d_in[0];
    const float* mat = (const float*)d_in[1];
    float* out = (float*)d_out;

    dim3 block(W, 1, 1);                 // 224 threads = 7 warps
    dim3 grid(1, H, B * (D / VPT));      // (1, 192, 80)
    affine_grid_sample_kernel<<<grid, block>>>(src, mat, out);
}